// round 12
// baseline (speedup 1.0000x reference)
#include <cuda_runtime.h>
#include <cuda_fp16.h>
#include <cuda_bf16.h>
#include <cstdint>

#define NN 200000
#define EE 6400000
#define CL 8          // cluster size
#define SHARD 25000   // NN / CL nodes per CTA shard
// R=3, B=5, H=16, C=8

// ---------------- scratch ----------------------------------------------------
__device__ float4 g_x4    [NN];           // (x0, x1, x2, 1.0) per node (f32, root path)
__device__ float4 g_sx    [3 * NN];       // per (r,dst): sum x + count in .w
__device__ uint4  g_xw2h  [3 * NN];       // [r][n][8] layer2 messages, fp16 (16B)
__device__ uint4  g_sums2h[3 * NN];       // per (r,dst) sums, layer2, fp16 (16B)
__device__ float4 g_rootx2[NN * 2];       // h@root2 + bias2
__device__ float  g_cpack [728];          // staging for all weights

// ---------------- constant weights (one packed bank, one memcpy) -------------
// Layout: W1[144] | W2[384] | root1[48] | bias1[16] | root2[128] | bias2[8]
__constant__ float c_pack[728];
#define CW1(i) c_pack[(i)]
#define CW2(i) c_pack[144 + (i)]
#define CR1(i) c_pack[528 + (i)]
#define CB1(i) c_pack[576 + (i)]
#define CR2(i) c_pack[592 + (i)]
#define CB2(i) c_pack[720 + (i)]

// ---------------- vectorized global reductions -------------------------------
__device__ __forceinline__ void red_add_v4(float4* addr, float4 v) {
    asm volatile("red.relaxed.gpu.global.add.v4.f32 [%0], {%1,%2,%3,%4};"
                 :: "l"(addr), "f"(v.x), "f"(v.y), "f"(v.z), "f"(v.w) : "memory");
}
__device__ __forceinline__ void red_add_v4h2(uint4* addr, uint4 v) {
    asm volatile("red.relaxed.gpu.global.add.noftz.v4.f16x2 [%0], {%1,%2,%3,%4};"
                 :: "l"(addr), "r"(v.x), "r"(v.y), "r"(v.z), "r"(v.w) : "memory");
}

__device__ __forceinline__ uint32_t smem_u32(const void* p) {
    uint32_t a;
    asm("{ .reg .u64 t; cvta.to.shared.u64 t, %1; cvt.u32.u64 %0, t; }" : "=r"(a) : "l"(p));
    return a;
}

// ---------------- kernels ----------------------------------------------------

// Fused prep: pack x (f32), zero g_sx, build weight pack (block 0).
__global__ void prep1(const float* __restrict__ x,
                      const float* __restrict__ b1, const float* __restrict__ c1,
                      const float* __restrict__ b2, const float* __restrict__ c2,
                      const float* __restrict__ r1, const float* __restrict__ bs1,
                      const float* __restrict__ r2, const float* __restrict__ bs2) {
    int n = blockIdx.x * blockDim.x + threadIdx.x;
    if (n < NN) {
        g_x4[n] = make_float4(x[n * 3 + 0], x[n * 3 + 1], x[n * 3 + 2], 1.0f);
        float4 z = make_float4(0.f, 0.f, 0.f, 0.f);
        g_sx[n] = z;
        g_sx[NN + n] = z;
        g_sx[2 * NN + n] = z;
    }
    if (blockIdx.x == 0) {
        for (int t = threadIdx.x; t < 144; t += blockDim.x) {  // W1: [r][i][o]
            int r = t / 48, rem = t % 48, i = rem / 16, o = rem % 16;
            float acc = 0.f;
            #pragma unroll
            for (int b = 0; b < 5; b++) acc += c1[r * 5 + b] * b1[(b * 3 + i) * 16 + o];
            g_cpack[t] = acc;
        }
        for (int t = threadIdx.x; t < 384; t += blockDim.x) {  // W2: [r][k][c]
            int r = t / 128, rem = t % 128, k = rem / 8, c = rem % 8;
            float acc = 0.f;
            #pragma unroll
            for (int b = 0; b < 5; b++) acc += c2[r * 5 + b] * b2[(b * 16 + k) * 8 + c];
            g_cpack[144 + t] = acc;
        }
        for (int t = threadIdx.x; t < 48; t += blockDim.x)  g_cpack[528 + t] = r1[t];
        for (int t = threadIdx.x; t < 16; t += blockDim.x)  g_cpack[576 + t] = bs1[t];
        for (int t = threadIdx.x; t < 128; t += blockDim.x) g_cpack[592 + t] = r2[t];
        for (int t = threadIdx.x; t < 8; t += blockDim.x)   g_cpack[720 + t] = bs2[t];
    }
}

// DSMEM gather helper: fetch fp16 (x0,x1,x2) of node s from the cluster shard.
__device__ __forceinline__ float4 gather_ds(uint32_t sh_base, int s) {
    unsigned owner = (unsigned)s / SHARD;
    unsigned off   = (unsigned)s - owner * SHARD;
    uint32_t addr = sh_base + off * 8u;
    uint32_t raddr;
    asm("mapa.shared::cluster.u32 %0, %1, %2;" : "=r"(raddr) : "r"(addr), "r"(owner));
    unsigned long long v;
    asm volatile("ld.shared::cluster.b64 %0, [%1];" : "=l"(v) : "r"(raddr));
    unsigned lo = (unsigned)v;
    __half2 h01 = *reinterpret_cast<__half2*>(&lo);
    float2 f01 = __half22float2(h01);
    float f2 = __half2float(__ushort_as_half((unsigned short)(v >> 32)));
    return make_float4(f01.x, f01.y, f2, 1.0f);
}

// Layer-1 edge scatter, cluster version: gather from DSMEM (no L2 txn),
// RED f32 to g_sx (1 L2 txn/edge). Full x table replicated per 8-CTA cluster.
__global__ void __cluster_dims__(CL, 1, 1) __launch_bounds__(512, 1)
scatter1_ds(const float* __restrict__ x,
            const int4* __restrict__ src4, const int4* __restrict__ dst4,
            const int4* __restrict__ et4) {
    extern __shared__ __align__(16) unsigned long long sh[];   // SHARD x 8B
    uint32_t rank;
    asm("mov.u32 %0, %%cluster_ctarank;" : "=r"(rank));

    // Fill this CTA's shard: nodes [rank*SHARD, (rank+1)*SHARD) as packed fp16.
    int base = rank * SHARD;
    for (int i = threadIdx.x; i < SHARD; i += blockDim.x) {
        const float* xr = x + (size_t)(base + i) * 3;
        unsigned long long p =
              (unsigned long long)__half_as_ushort(__float2half_rn(xr[0]))
            | ((unsigned long long)__half_as_ushort(__float2half_rn(xr[1])) << 16)
            | ((unsigned long long)__half_as_ushort(__float2half_rn(xr[2])) << 32);
        sh[i] = p;
    }
    asm volatile("barrier.cluster.arrive.aligned;" ::: "memory");
    asm volatile("barrier.cluster.wait.aligned;" ::: "memory");

    uint32_t sh_base = smem_u32(sh);
    int tid = blockIdx.x * blockDim.x + threadIdx.x;
    int nth = gridDim.x * blockDim.x;
    for (int t = tid; t < EE / 4; t += nth) {
        int4 s = src4[t], d = dst4[t], r = et4[t];
        float4 v0 = gather_ds(sh_base, s.x);
        float4 v1 = gather_ds(sh_base, s.y);
        float4 v2 = gather_ds(sh_base, s.z);
        float4 v3 = gather_ds(sh_base, s.w);
        red_add_v4(&g_sx[r.x * NN + d.x], v0);
        red_add_v4(&g_sx[r.y * NN + d.y], v1);
        red_add_v4(&g_sx[r.z * NN + d.z], v2);
        red_add_v4(&g_sx[r.w * NN + d.w], v3);
    }

    // No CTA may exit while cluster peers still read its smem.
    asm volatile("barrier.cluster.arrive.aligned;" ::: "memory");
    asm volatile("barrier.cluster.wait.aligned;" ::: "memory");
}

// Fused: layer-1 finalize + layer-2 dense (f32) + zero fp16 sums inline (R9).
__global__ void fin1dense2() {
    int n = blockIdx.x * blockDim.x + threadIdx.x;
    if (n >= NN) return;
    float h[16];
    #pragma unroll
    for (int o = 0; o < 16; o++) h[o] = CB1(o);
    float4 xv = g_x4[n];
    float xi[3] = {xv.x, xv.y, xv.z};
    #pragma unroll
    for (int i = 0; i < 3; i++)
        #pragma unroll
        for (int o = 0; o < 16; o++) h[o] += xi[i] * CR1(i * 16 + o);
    #pragma unroll
    for (int r = 0; r < 3; r++) {
        float4 s = g_sx[r * NN + n];
        float inv = 1.0f / fmaxf(s.w, 1.0f);
        float m[3] = {s.x * inv, s.y * inv, s.z * inv};
        #pragma unroll
        for (int i = 0; i < 3; i++)
            #pragma unroll
            for (int o = 0; o < 16; o++) h[o] += m[i] * CW1(r * 48 + i * 16 + o);
    }
    #pragma unroll
    for (int o = 0; o < 16; o++) h[o] = fmaxf(h[o], 0.f);

    uint4 z = make_uint4(0u, 0u, 0u, 0u);
    #pragma unroll
    for (int r = 0; r < 3; r++) {
        float acc[8];
        #pragma unroll
        for (int c = 0; c < 8; c++) acc[c] = 0.f;
        #pragma unroll
        for (int k = 0; k < 16; k++)
            #pragma unroll
            for (int c = 0; c < 8; c++) acc[c] += h[k] * CW2(r * 128 + k * 8 + c);
        __half2 p0 = __float22half2_rn(make_float2(acc[0], acc[1]));
        __half2 p1 = __float22half2_rn(make_float2(acc[2], acc[3]));
        __half2 p2 = __float22half2_rn(make_float2(acc[4], acc[5]));
        __half2 p3 = __float22half2_rn(make_float2(acc[6], acc[7]));
        uint4 packed;
        packed.x = *reinterpret_cast<unsigned*>(&p0);
        packed.y = *reinterpret_cast<unsigned*>(&p1);
        packed.z = *reinterpret_cast<unsigned*>(&p2);
        packed.w = *reinterpret_cast<unsigned*>(&p3);
        g_xw2h[r * NN + n] = packed;
        g_sums2h[r * NN + n] = z;          // zero fp16 accumulator inline
    }
    float acc[8];
    #pragma unroll
    for (int c = 0; c < 8; c++) acc[c] = CB2(c);
    #pragma unroll
    for (int k = 0; k < 16; k++)
        #pragma unroll
        for (int c = 0; c < 8; c++) acc[c] += h[k] * CR2(k * 8 + c);
    g_rootx2[n * 2 + 0] = make_float4(acc[0], acc[1], acc[2], acc[3]);
    g_rootx2[n * 2 + 1] = make_float4(acc[4], acc[5], acc[6], acc[7]);
}

// Layer-2 edge scatter: 4 edges/thread, 1 gather + 1 fp16 RED per edge.
__global__ void scatter2(const int4* __restrict__ src4, const int4* __restrict__ dst4,
                         const int4* __restrict__ et4) {
    int t = blockIdx.x * blockDim.x + threadIdx.x;
    if (t >= EE / 4) return;
    int4 s = src4[t], d = dst4[t], r = et4[t];
    uint4 p0 = __ldg(&g_xw2h[r.x * NN + s.x]);
    uint4 p1 = __ldg(&g_xw2h[r.y * NN + s.y]);
    uint4 p2 = __ldg(&g_xw2h[r.z * NN + s.z]);
    uint4 p3 = __ldg(&g_xw2h[r.w * NN + s.w]);
    red_add_v4h2(&g_sums2h[r.x * NN + d.x], p0);
    red_add_v4h2(&g_sums2h[r.y * NN + d.y], p1);
    red_add_v4h2(&g_sums2h[r.z * NN + d.z], p2);
    red_add_v4h2(&g_sums2h[r.w * NN + d.w], p3);
}

// Layer-2 finalize + log_softmax. One thread per node. Counts from g_sx.w.
__global__ void finalize2(float* __restrict__ out) {
    int n = blockIdx.x * blockDim.x + threadIdx.x;
    if (n >= NN) return;
    float v[8];
    {
        float4 a = g_rootx2[n * 2 + 0], b = g_rootx2[n * 2 + 1];
        v[0]=a.x; v[1]=a.y; v[2]=a.z; v[3]=a.w;
        v[4]=b.x; v[5]=b.y; v[6]=b.z; v[7]=b.w;
    }
    #pragma unroll
    for (int r = 0; r < 3; r++) {
        float inv = 1.0f / fmaxf(g_sx[r * NN + n].w, 1.0f);
        uint4 p = g_sums2h[r * NN + n];
        float2 f0 = __half22float2(*reinterpret_cast<__half2*>(&p.x));
        float2 f1 = __half22float2(*reinterpret_cast<__half2*>(&p.y));
        float2 f2 = __half22float2(*reinterpret_cast<__half2*>(&p.z));
        float2 f3 = __half22float2(*reinterpret_cast<__half2*>(&p.w));
        v[0] += f0.x*inv; v[1] += f0.y*inv; v[2] += f1.x*inv; v[3] += f1.y*inv;
        v[4] += f2.x*inv; v[5] += f2.y*inv; v[6] += f3.x*inv; v[7] += f3.y*inv;
    }
    float m = v[0];
    #pragma unroll
    for (int i = 1; i < 8; i++) m = fmaxf(m, v[i]);
    float s = 0.f;
    #pragma unroll
    for (int i = 0; i < 8; i++) s += expf(v[i] - m);
    float lse = m + logf(s);
    float4* o = (float4*)(out + (size_t)n * 8);
    o[0] = make_float4(v[0]-lse, v[1]-lse, v[2]-lse, v[3]-lse);
    o[1] = make_float4(v[4]-lse, v[5]-lse, v[6]-lse, v[7]-lse);
}

// ---------------- host -------------------------------------------------------
extern "C" void kernel_launch(void* const* d_in, const int* in_sizes, int n_in,
                              void* d_out, int out_size) {
    const float *x = nullptr, *b1 = nullptr, *c1 = nullptr, *r1 = nullptr, *bs1 = nullptr;
    const float *b2 = nullptr, *c2 = nullptr, *r2 = nullptr, *bs2 = nullptr;
    const int *ei = nullptr, *et = nullptr;
    for (int i = 0; i < n_in; i++) {
        switch (in_sizes[i]) {
            case NN * 3:      x   = (const float*)d_in[i]; break;
            case 2 * EE:      ei  = (const int*)d_in[i];   break;
            case EE:          et  = (const int*)d_in[i];   break;
            case 5 * 3 * 16:  b1  = (const float*)d_in[i]; break;
            case 3 * 16:      r1  = (const float*)d_in[i]; break;
            case 16:          bs1 = (const float*)d_in[i]; break;
            case 5 * 16 * 8:  b2  = (const float*)d_in[i]; break;
            case 16 * 8:      r2  = (const float*)d_in[i]; break;
            case 8:           bs2 = (const float*)d_in[i]; break;
            case 15:          if (!c1) c1 = (const float*)d_in[i];
                              else     c2 = (const float*)d_in[i]; break;
            default: break;
        }
    }
    const int4* src4 = (const int4*)ei;
    const int4* dst4 = (const int4*)(ei + EE);
    const int4* et4  = (const int4*)et;
    float* out = (float*)d_out;

    // Lazy resource creation (first call is uncaptured correctness run).
    static cudaStream_t s_side = nullptr;
    static cudaEvent_t  e_prep = nullptr, e_cpy = nullptr;
    static void* a_cpack = nullptr;
    if (!s_side) {
        cudaStreamCreateWithFlags(&s_side, cudaStreamNonBlocking);
        cudaEventCreateWithFlags(&e_prep, cudaEventDisableTiming);
        cudaEventCreateWithFlags(&e_cpy,  cudaEventDisableTiming);
        cudaGetSymbolAddress(&a_cpack, g_cpack);
        cudaFuncSetAttribute(scatter1_ds,
                             cudaFuncAttributeMaxDynamicSharedMemorySize, SHARD * 8);
    }

    const int T = 256;

    prep1<<<(NN + T - 1) / T, T>>>(x, b1, c1, b2, c2, r1, bs1, r2, bs2);

    // Single weight memcpy on side stream — hidden behind scatter1.
    cudaEventRecord(e_prep, 0);
    cudaStreamWaitEvent(s_side, e_prep, 0);
    cudaMemcpyToSymbolAsync(c_pack, a_cpack, 728 * sizeof(float), 0,
                            cudaMemcpyDeviceToDevice, s_side);
    cudaEventRecord(e_cpy, s_side);

    // Cluster scatter1: 18 clusters x 8 CTAs x 512 threads, 200KB smem/CTA.
    scatter1_ds<<<144, 512, SHARD * 8>>>(x, src4, dst4, et4);

    cudaStreamWaitEvent(0, e_cpy, 0);
    fin1dense2<<<(NN + T - 1) / T, T>>>();
    scatter2<<<(EE / 4) / T, T>>>(src4, dst4, et4);
    finalize2<<<(NN + T - 1) / T, T>>>(out);
    (void)out_size;
}

// round 13
// speedup vs baseline: 2.0600x; 2.0600x over previous
#include <cuda_runtime.h>
#include <cuda_fp16.h>
#include <cuda_bf16.h>
#include <cstdint>

#define NN 200000
#define EE 6400000
// R=3, B=5, H=16, C=8

// ---------------- scratch ----------------------------------------------------
__device__ float4 g_x4    [NN];           // (x0, x1, x2, 1.0) per node
__device__ float4 g_sx    [3 * NN];       // per (r,dst): sum x + count in .w
__device__ uint4  g_xw2h  [3 * NN];       // [r][n][8] layer2 messages, fp16 (16B)
__device__ uint4  g_sums2h[3 * NN];       // per (r,dst) sums, layer2, fp16 (16B)
__device__ float4 g_rootx2[NN * 2];       // h@root2 + bias2
__device__ float  g_cpack [728];          // staging for all weights

// ---------------- constant weights (one packed bank, one memcpy) -------------
// Layout: W1[144] | W2[384] | root1[48] | bias1[16] | root2[128] | bias2[8]
__constant__ float c_pack[728];
#define CW1(i) c_pack[(i)]
#define CW2(i) c_pack[144 + (i)]
#define CR1(i) c_pack[528 + (i)]
#define CB1(i) c_pack[576 + (i)]
#define CR2(i) c_pack[592 + (i)]
#define CB2(i) c_pack[720 + (i)]

// ---------------- vectorized global reductions -------------------------------
__device__ __forceinline__ void red_add_v4(float4* addr, float4 v) {
    asm volatile("red.relaxed.gpu.global.add.v4.f32 [%0], {%1,%2,%3,%4};"
                 :: "l"(addr), "f"(v.x), "f"(v.y), "f"(v.z), "f"(v.w) : "memory");
}
__device__ __forceinline__ void red_add_v4h2(uint4* addr, uint4 v) {
    asm volatile("red.relaxed.gpu.global.add.noftz.v4.f16x2 [%0], {%1,%2,%3,%4};"
                 :: "l"(addr), "r"(v.x), "r"(v.y), "r"(v.z), "r"(v.w) : "memory");
}

// ---------------- kernels ----------------------------------------------------

// Fused prep: pack x, zero g_sx, build weight pack (block 0).
__global__ void prep1(const float* __restrict__ x,
                      const float* __restrict__ b1, const float* __restrict__ c1,
                      const float* __restrict__ b2, const float* __restrict__ c2,
                      const float* __restrict__ r1, const float* __restrict__ bs1,
                      const float* __restrict__ r2, const float* __restrict__ bs2) {
    int n = blockIdx.x * blockDim.x + threadIdx.x;
    if (n < NN) {
        g_x4[n] = make_float4(x[n * 3 + 0], x[n * 3 + 1], x[n * 3 + 2], 1.0f);
        float4 z = make_float4(0.f, 0.f, 0.f, 0.f);
        g_sx[n] = z;
        g_sx[NN + n] = z;
        g_sx[2 * NN + n] = z;
    }
    if (blockIdx.x == 0) {
        for (int t = threadIdx.x; t < 144; t += blockDim.x) {  // W1: [r][i][o]
            int r = t / 48, rem = t % 48, i = rem / 16, o = rem % 16;
            float acc = 0.f;
            #pragma unroll
            for (int b = 0; b < 5; b++) acc += c1[r * 5 + b] * b1[(b * 3 + i) * 16 + o];
            g_cpack[t] = acc;
        }
        for (int t = threadIdx.x; t < 384; t += blockDim.x) {  // W2: [r][k][c]
            int r = t / 128, rem = t % 128, k = rem / 8, c = rem % 8;
            float acc = 0.f;
            #pragma unroll
            for (int b = 0; b < 5; b++) acc += c2[r * 5 + b] * b2[(b * 16 + k) * 8 + c];
            g_cpack[144 + t] = acc;
        }
        for (int t = threadIdx.x; t < 48; t += blockDim.x)  g_cpack[528 + t] = r1[t];
        for (int t = threadIdx.x; t < 16; t += blockDim.x)  g_cpack[576 + t] = bs1[t];
        for (int t = threadIdx.x; t < 128; t += blockDim.x) g_cpack[592 + t] = r2[t];
        for (int t = threadIdx.x; t < 8; t += blockDim.x)   g_cpack[720 + t] = bs2[t];
    }
}

// Layer-1 edge scatter: 4 edges/thread, int4 index loads (R9).
__global__ void scatter1(const int4* __restrict__ src4, const int4* __restrict__ dst4,
                         const int4* __restrict__ et4) {
    int t = blockIdx.x * blockDim.x + threadIdx.x;
    if (t >= EE / 4) return;
    int4 s = src4[t], d = dst4[t], r = et4[t];
    float4 v0 = __ldg(&g_x4[s.x]);
    float4 v1 = __ldg(&g_x4[s.y]);
    float4 v2 = __ldg(&g_x4[s.z]);
    float4 v3 = __ldg(&g_x4[s.w]);
    red_add_v4(&g_sx[r.x * NN + d.x], v0);
    red_add_v4(&g_sx[r.y * NN + d.y], v1);
    red_add_v4(&g_sx[r.z * NN + d.z], v2);
    red_add_v4(&g_sx[r.w * NN + d.w], v3);
}

// Shared h computation: layer-1 finalize for node n (registers).
__device__ __forceinline__ void compute_h(int n, float* h) {
    #pragma unroll
    for (int o = 0; o < 16; o++) h[o] = CB1(o);
    float4 xv = g_x4[n];
    float xi[3] = {xv.x, xv.y, xv.z};
    #pragma unroll
    for (int i = 0; i < 3; i++)
        #pragma unroll
        for (int o = 0; o < 16; o++) h[o] += xi[i] * CR1(i * 16 + o);
    #pragma unroll
    for (int r = 0; r < 3; r++) {
        float4 s = g_sx[r * NN + n];
        float inv = 1.0f / fmaxf(s.w, 1.0f);
        float m[3] = {s.x * inv, s.y * inv, s.z * inv};
        #pragma unroll
        for (int i = 0; i < 3; i++)
            #pragma unroll
            for (int o = 0; o < 16; o++) h[o] += m[i] * CW1(r * 48 + i * 16 + o);
    }
    #pragma unroll
    for (int o = 0; o < 16; o++) h[o] = fmaxf(h[o], 0.f);
}

// Fused layer-1 finalize + layer-2 dense, 4 threads/node (j = gid/NN):
//   j in {0,1,2}: compute fp16 message for relation j + zero its accumulator.
//   j == 3:       compute rootx2.
// j is warp-uniform (blocked decomposition), n coalesced.
__global__ void fin1dense2() {
    int gid = blockIdx.x * blockDim.x + threadIdx.x;
    if (gid >= 4 * NN) return;
    int j = gid / NN;
    int n = gid - j * NN;
    float h[16];
    compute_h(n, h);
    if (j < 3) {
        float acc[8];
        #pragma unroll
        for (int c = 0; c < 8; c++) acc[c] = 0.f;
        #pragma unroll
        for (int k = 0; k < 16; k++)
            #pragma unroll
            for (int c = 0; c < 8; c++) acc[c] += h[k] * CW2(j * 128 + k * 8 + c);
        __half2 p0 = __float22half2_rn(make_float2(acc[0], acc[1]));
        __half2 p1 = __float22half2_rn(make_float2(acc[2], acc[3]));
        __half2 p2 = __float22half2_rn(make_float2(acc[4], acc[5]));
        __half2 p3 = __float22half2_rn(make_float2(acc[6], acc[7]));
        uint4 packed;
        packed.x = *reinterpret_cast<unsigned*>(&p0);
        packed.y = *reinterpret_cast<unsigned*>(&p1);
        packed.z = *reinterpret_cast<unsigned*>(&p2);
        packed.w = *reinterpret_cast<unsigned*>(&p3);
        g_xw2h[j * NN + n] = packed;
        g_sums2h[j * NN + n] = make_uint4(0u, 0u, 0u, 0u);
    } else {
        float acc[8];
        #pragma unroll
        for (int c = 0; c < 8; c++) acc[c] = CB2(c);
        #pragma unroll
        for (int k = 0; k < 16; k++)
            #pragma unroll
            for (int c = 0; c < 8; c++) acc[c] += h[k] * CR2(k * 8 + c);
        g_rootx2[n * 2 + 0] = make_float4(acc[0], acc[1], acc[2], acc[3]);
        g_rootx2[n * 2 + 1] = make_float4(acc[4], acc[5], acc[6], acc[7]);
    }
}

// Layer-2 edge scatter: 4 edges/thread, 1 gather + 1 fp16 RED per edge (R9).
__global__ void scatter2(const int4* __restrict__ src4, const int4* __restrict__ dst4,
                         const int4* __restrict__ et4) {
    int t = blockIdx.x * blockDim.x + threadIdx.x;
    if (t >= EE / 4) return;
    int4 s = src4[t], d = dst4[t], r = et4[t];
    uint4 p0 = __ldg(&g_xw2h[r.x * NN + s.x]);
    uint4 p1 = __ldg(&g_xw2h[r.y * NN + s.y]);
    uint4 p2 = __ldg(&g_xw2h[r.z * NN + s.z]);
    uint4 p3 = __ldg(&g_xw2h[r.w * NN + s.w]);
    red_add_v4h2(&g_sums2h[r.x * NN + d.x], p0);
    red_add_v4h2(&g_sums2h[r.y * NN + d.y], p1);
    red_add_v4h2(&g_sums2h[r.z * NN + d.z], p2);
    red_add_v4h2(&g_sums2h[r.w * NN + d.w], p3);
}

// Layer-2 finalize + log_softmax. One thread per node. Counts from g_sx.w.
__global__ void finalize2(float* __restrict__ out) {
    int n = blockIdx.x * blockDim.x + threadIdx.x;
    if (n >= NN) return;
    float v[8];
    {
        float4 a = g_rootx2[n * 2 + 0], b = g_rootx2[n * 2 + 1];
        v[0]=a.x; v[1]=a.y; v[2]=a.z; v[3]=a.w;
        v[4]=b.x; v[5]=b.y; v[6]=b.z; v[7]=b.w;
    }
    #pragma unroll
    for (int r = 0; r < 3; r++) {
        float inv = 1.0f / fmaxf(g_sx[r * NN + n].w, 1.0f);
        uint4 p = g_sums2h[r * NN + n];
        float2 f0 = __half22float2(*reinterpret_cast<__half2*>(&p.x));
        float2 f1 = __half22float2(*reinterpret_cast<__half2*>(&p.y));
        float2 f2 = __half22float2(*reinterpret_cast<__half2*>(&p.z));
        float2 f3 = __half22float2(*reinterpret_cast<__half2*>(&p.w));
        v[0] += f0.x*inv; v[1] += f0.y*inv; v[2] += f1.x*inv; v[3] += f1.y*inv;
        v[4] += f2.x*inv; v[5] += f2.y*inv; v[6] += f3.x*inv; v[7] += f3.y*inv;
    }
    float m = v[0];
    #pragma unroll
    for (int i = 1; i < 8; i++) m = fmaxf(m, v[i]);
    float s = 0.f;
    #pragma unroll
    for (int i = 0; i < 8; i++) s += expf(v[i] - m);
    float lse = m + logf(s);
    float4* o = (float4*)(out + (size_t)n * 8);
    o[0] = make_float4(v[0]-lse, v[1]-lse, v[2]-lse, v[3]-lse);
    o[1] = make_float4(v[4]-lse, v[5]-lse, v[6]-lse, v[7]-lse);
}

// ---------------- host -------------------------------------------------------
extern "C" void kernel_launch(void* const* d_in, const int* in_sizes, int n_in,
                              void* d_out, int out_size) {
    const float *x = nullptr, *b1 = nullptr, *c1 = nullptr, *r1 = nullptr, *bs1 = nullptr;
    const float *b2 = nullptr, *c2 = nullptr, *r2 = nullptr, *bs2 = nullptr;
    const int *ei = nullptr, *et = nullptr;
    for (int i = 0; i < n_in; i++) {
        switch (in_sizes[i]) {
            case NN * 3:      x   = (const float*)d_in[i]; break;
            case 2 * EE:      ei  = (const int*)d_in[i];   break;
            case EE:          et  = (const int*)d_in[i];   break;
            case 5 * 3 * 16:  b1  = (const float*)d_in[i]; break;
            case 3 * 16:      r1  = (const float*)d_in[i]; break;
            case 16:          bs1 = (const float*)d_in[i]; break;
            case 5 * 16 * 8:  b2  = (const float*)d_in[i]; break;
            case 16 * 8:      r2  = (const float*)d_in[i]; break;
            case 8:           bs2 = (const float*)d_in[i]; break;
            case 15:          if (!c1) c1 = (const float*)d_in[i];
                              else     c2 = (const float*)d_in[i]; break;
            default: break;
        }
    }
    const int4* src4 = (const int4*)ei;
    const int4* dst4 = (const int4*)(ei + EE);
    const int4* et4  = (const int4*)et;
    float* out = (float*)d_out;

    // Lazy resource creation (first call is uncaptured correctness run).
    static cudaStream_t s_side = nullptr;
    static cudaEvent_t  e_prep = nullptr, e_cpy = nullptr;
    static void* a_cpack = nullptr;
    if (!s_side) {
        cudaStreamCreateWithFlags(&s_side, cudaStreamNonBlocking);
        cudaEventCreateWithFlags(&e_prep, cudaEventDisableTiming);
        cudaEventCreateWithFlags(&e_cpy,  cudaEventDisableTiming);
        cudaGetSymbolAddress(&a_cpack, g_cpack);
    }

    const int T = 256;

    prep1<<<(NN + T - 1) / T, T>>>(x, b1, c1, b2, c2, r1, bs1, r2, bs2);

    // Single weight memcpy on side stream — hidden behind scatter1.
    cudaEventRecord(e_prep, 0);
    cudaStreamWaitEvent(s_side, e_prep, 0);
    cudaMemcpyToSymbolAsync(c_pack, a_cpack, 728 * sizeof(float), 0,
                            cudaMemcpyDeviceToDevice, s_side);
    cudaEventRecord(e_cpy, s_side);

    scatter1<<<(EE / 4) / T, T>>>(src4, dst4, et4);

    cudaStreamWaitEvent(0, e_cpy, 0);
    fin1dense2<<<(4 * NN + T - 1) / T, T>>>();
    scatter2<<<(EE / 4) / T, T>>>(src4, dst4, et4);
    finalize2<<<(NN + T - 1) / T, T>>>(out);
    (void)out_size;
}

// round 14
// speedup vs baseline: 2.2130x; 1.0743x over previous
#include <cuda_runtime.h>
#include <cuda_fp16.h>
#include <cuda_bf16.h>
#include <cstdint>

#define NN 200000
#define EE 6400000
// R=3, B=5, H=16, C=8

// ---------------- scratch ----------------------------------------------------
__device__ float4 g_x4     [NN];          // (x0, x1, x2, 1.0) per node
__device__ float4 g_sx     [3 * NN];      // per (r,dst): sum x + count in .w
__device__ uint4  g_xw2h   [3 * NN];      // [r][n][8] layer2 messages, fp16 (16B)
__device__ uint4  g_sums2h [3 * NN];      // per (r,dst) sums, layer2, fp16 (16B)
__device__ uint4  g_rootx2h[NN];          // h@root2 + bias2, fp16 (16B)
__device__ float  g_cpack  [728];         // staging for all weights

// ---------------- constant weights (one packed bank, one memcpy) -------------
// Layout: W1[144] | W2[384] | root1[48] | bias1[16] | root2[128] | bias2[8]
__constant__ float c_pack[728];
#define CW1(i) c_pack[(i)]
#define CW2(i) c_pack[144 + (i)]
#define CR1(i) c_pack[528 + (i)]
#define CB1(i) c_pack[576 + (i)]
#define CR2(i) c_pack[592 + (i)]
#define CB2(i) c_pack[720 + (i)]

// ---------------- vectorized global reductions -------------------------------
__device__ __forceinline__ void red_add_v4(float4* addr, float4 v) {
    asm volatile("red.relaxed.gpu.global.add.v4.f32 [%0], {%1,%2,%3,%4};"
                 :: "l"(addr), "f"(v.x), "f"(v.y), "f"(v.z), "f"(v.w) : "memory");
}
__device__ __forceinline__ void red_add_v4h2(uint4* addr, uint4 v) {
    asm volatile("red.relaxed.gpu.global.add.noftz.v4.f16x2 [%0], {%1,%2,%3,%4};"
                 :: "l"(addr), "r"(v.x), "r"(v.y), "r"(v.z), "r"(v.w) : "memory");
}

// ---------------- kernels ----------------------------------------------------

// Fused prep: pack x, zero g_sx, build weight pack (block 0).
__global__ void prep1(const float* __restrict__ x,
                      const float* __restrict__ b1, const float* __restrict__ c1,
                      const float* __restrict__ b2, const float* __restrict__ c2,
                      const float* __restrict__ r1, const float* __restrict__ bs1,
                      const float* __restrict__ r2, const float* __restrict__ bs2) {
    int n = blockIdx.x * blockDim.x + threadIdx.x;
    if (n < NN) {
        g_x4[n] = make_float4(x[n * 3 + 0], x[n * 3 + 1], x[n * 3 + 2], 1.0f);
        float4 z = make_float4(0.f, 0.f, 0.f, 0.f);
        g_sx[n] = z;
        g_sx[NN + n] = z;
        g_sx[2 * NN + n] = z;
    }
    if (blockIdx.x == 0) {
        for (int t = threadIdx.x; t < 144; t += blockDim.x) {  // W1: [r][i][o]
            int r = t / 48, rem = t % 48, i = rem / 16, o = rem % 16;
            float acc = 0.f;
            #pragma unroll
            for (int b = 0; b < 5; b++) acc += c1[r * 5 + b] * b1[(b * 3 + i) * 16 + o];
            g_cpack[t] = acc;
        }
        for (int t = threadIdx.x; t < 384; t += blockDim.x) {  // W2: [r][k][c]
            int r = t / 128, rem = t % 128, k = rem / 8, c = rem % 8;
            float acc = 0.f;
            #pragma unroll
            for (int b = 0; b < 5; b++) acc += c2[r * 5 + b] * b2[(b * 16 + k) * 8 + c];
            g_cpack[144 + t] = acc;
        }
        for (int t = threadIdx.x; t < 48; t += blockDim.x)  g_cpack[528 + t] = r1[t];
        for (int t = threadIdx.x; t < 16; t += blockDim.x)  g_cpack[576 + t] = bs1[t];
        for (int t = threadIdx.x; t < 128; t += blockDim.x) g_cpack[592 + t] = r2[t];
        for (int t = threadIdx.x; t < 8; t += blockDim.x)   g_cpack[720 + t] = bs2[t];
    }
}

// Layer-1 edge scatter: 4 edges/thread, int4 index loads.
// Piggyback: first 600K threads zero one uint4 of g_sums2h (coalesced stream,
// hidden in scatter1's idle issue slots; ordering via kernel boundary).
__global__ void scatter1(const int4* __restrict__ src4, const int4* __restrict__ dst4,
                         const int4* __restrict__ et4) {
    int t = blockIdx.x * blockDim.x + threadIdx.x;
    if (t >= EE / 4) return;
    if (t < 3 * NN) g_sums2h[t] = make_uint4(0u, 0u, 0u, 0u);
    int4 s = src4[t], d = dst4[t], r = et4[t];
    float4 v0 = __ldg(&g_x4[s.x]);
    float4 v1 = __ldg(&g_x4[s.y]);
    float4 v2 = __ldg(&g_x4[s.z]);
    float4 v3 = __ldg(&g_x4[s.w]);
    red_add_v4(&g_sx[r.x * NN + d.x], v0);
    red_add_v4(&g_sx[r.y * NN + d.y], v1);
    red_add_v4(&g_sx[r.z * NN + d.z], v2);
    red_add_v4(&g_sx[r.w * NN + d.w], v3);
}

// Fused layer-1 finalize + layer-2 dense: 4 STG.128/node
// (3 fp16 messages + 1 fp16 rootx2; sums2h zeroed by scatter1).
__global__ void fin1dense2() {
    int n = blockIdx.x * blockDim.x + threadIdx.x;
    if (n >= NN) return;
    float h[16];
    #pragma unroll
    for (int o = 0; o < 16; o++) h[o] = CB1(o);
    float4 xv = g_x4[n];
    float xi[3] = {xv.x, xv.y, xv.z};
    #pragma unroll
    for (int i = 0; i < 3; i++)
        #pragma unroll
        for (int o = 0; o < 16; o++) h[o] += xi[i] * CR1(i * 16 + o);
    #pragma unroll
    for (int r = 0; r < 3; r++) {
        float4 s = g_sx[r * NN + n];
        float inv = 1.0f / fmaxf(s.w, 1.0f);
        float m[3] = {s.x * inv, s.y * inv, s.z * inv};
        #pragma unroll
        for (int i = 0; i < 3; i++)
            #pragma unroll
            for (int o = 0; o < 16; o++) h[o] += m[i] * CW1(r * 48 + i * 16 + o);
    }
    #pragma unroll
    for (int o = 0; o < 16; o++) h[o] = fmaxf(h[o], 0.f);

    #pragma unroll
    for (int r = 0; r < 3; r++) {
        float acc[8];
        #pragma unroll
        for (int c = 0; c < 8; c++) acc[c] = 0.f;
        #pragma unroll
        for (int k = 0; k < 16; k++)
            #pragma unroll
            for (int c = 0; c < 8; c++) acc[c] += h[k] * CW2(r * 128 + k * 8 + c);
        __half2 p0 = __float22half2_rn(make_float2(acc[0], acc[1]));
        __half2 p1 = __float22half2_rn(make_float2(acc[2], acc[3]));
        __half2 p2 = __float22half2_rn(make_float2(acc[4], acc[5]));
        __half2 p3 = __float22half2_rn(make_float2(acc[6], acc[7]));
        uint4 packed;
        packed.x = *reinterpret_cast<unsigned*>(&p0);
        packed.y = *reinterpret_cast<unsigned*>(&p1);
        packed.z = *reinterpret_cast<unsigned*>(&p2);
        packed.w = *reinterpret_cast<unsigned*>(&p3);
        g_xw2h[r * NN + n] = packed;
    }
    float acc[8];
    #pragma unroll
    for (int c = 0; c < 8; c++) acc[c] = CB2(c);
    #pragma unroll
    for (int k = 0; k < 16; k++)
        #pragma unroll
        for (int c = 0; c < 8; c++) acc[c] += h[k] * CR2(k * 8 + c);
    __half2 q0 = __float22half2_rn(make_float2(acc[0], acc[1]));
    __half2 q1 = __float22half2_rn(make_float2(acc[2], acc[3]));
    __half2 q2 = __float22half2_rn(make_float2(acc[4], acc[5]));
    __half2 q3 = __float22half2_rn(make_float2(acc[6], acc[7]));
    uint4 rp;
    rp.x = *reinterpret_cast<unsigned*>(&q0);
    rp.y = *reinterpret_cast<unsigned*>(&q1);
    rp.z = *reinterpret_cast<unsigned*>(&q2);
    rp.w = *reinterpret_cast<unsigned*>(&q3);
    g_rootx2h[n] = rp;
}

// Layer-2 edge scatter: 4 edges/thread, 1 gather + 1 fp16 RED per edge.
__global__ void scatter2(const int4* __restrict__ src4, const int4* __restrict__ dst4,
                         const int4* __restrict__ et4) {
    int t = blockIdx.x * blockDim.x + threadIdx.x;
    if (t >= EE / 4) return;
    int4 s = src4[t], d = dst4[t], r = et4[t];
    uint4 p0 = __ldg(&g_xw2h[r.x * NN + s.x]);
    uint4 p1 = __ldg(&g_xw2h[r.y * NN + s.y]);
    uint4 p2 = __ldg(&g_xw2h[r.z * NN + s.z]);
    uint4 p3 = __ldg(&g_xw2h[r.w * NN + s.w]);
    red_add_v4h2(&g_sums2h[r.x * NN + d.x], p0);
    red_add_v4h2(&g_sums2h[r.y * NN + d.y], p1);
    red_add_v4h2(&g_sums2h[r.z * NN + d.z], p2);
    red_add_v4h2(&g_sums2h[r.w * NN + d.w], p3);
}

// Layer-2 finalize + log_softmax. One thread per node. Counts from g_sx.w.
__global__ void finalize2(float* __restrict__ out) {
    int n = blockIdx.x * blockDim.x + threadIdx.x;
    if (n >= NN) return;
    float v[8];
    {
        uint4 rp = g_rootx2h[n];
        float2 a = __half22float2(*reinterpret_cast<__half2*>(&rp.x));
        float2 b = __half22float2(*reinterpret_cast<__half2*>(&rp.y));
        float2 c = __half22float2(*reinterpret_cast<__half2*>(&rp.z));
        float2 dd = __half22float2(*reinterpret_cast<__half2*>(&rp.w));
        v[0]=a.x; v[1]=a.y; v[2]=b.x; v[3]=b.y;
        v[4]=c.x; v[5]=c.y; v[6]=dd.x; v[7]=dd.y;
    }
    #pragma unroll
    for (int r = 0; r < 3; r++) {
        float inv = 1.0f / fmaxf(g_sx[r * NN + n].w, 1.0f);
        uint4 p = g_sums2h[r * NN + n];
        float2 f0 = __half22float2(*reinterpret_cast<__half2*>(&p.x));
        float2 f1 = __half22float2(*reinterpret_cast<__half2*>(&p.y));
        float2 f2 = __half22float2(*reinterpret_cast<__half2*>(&p.z));
        float2 f3 = __half22float2(*reinterpret_cast<__half2*>(&p.w));
        v[0] += f0.x*inv; v[1] += f0.y*inv; v[2] += f1.x*inv; v[3] += f1.y*inv;
        v[4] += f2.x*inv; v[5] += f2.y*inv; v[6] += f3.x*inv; v[7] += f3.y*inv;
    }
    float m = v[0];
    #pragma unroll
    for (int i = 1; i < 8; i++) m = fmaxf(m, v[i]);
    float s = 0.f;
    #pragma unroll
    for (int i = 0; i < 8; i++) s += expf(v[i] - m);
    float lse = m + logf(s);
    float4* o = (float4*)(out + (size_t)n * 8);
    o[0] = make_float4(v[0]-lse, v[1]-lse, v[2]-lse, v[3]-lse);
    o[1] = make_float4(v[4]-lse, v[5]-lse, v[6]-lse, v[7]-lse);
}

// ---------------- host -------------------------------------------------------
extern "C" void kernel_launch(void* const* d_in, const int* in_sizes, int n_in,
                              void* d_out, int out_size) {
    const float *x = nullptr, *b1 = nullptr, *c1 = nullptr, *r1 = nullptr, *bs1 = nullptr;
    const float *b2 = nullptr, *c2 = nullptr, *r2 = nullptr, *bs2 = nullptr;
    const int *ei = nullptr, *et = nullptr;
    for (int i = 0; i < n_in; i++) {
        switch (in_sizes[i]) {
            case NN * 3:      x   = (const float*)d_in[i]; break;
            case 2 * EE:      ei  = (const int*)d_in[i];   break;
            case EE:          et  = (const int*)d_in[i];   break;
            case 5 * 3 * 16:  b1  = (const float*)d_in[i]; break;
            case 3 * 16:      r1  = (const float*)d_in[i]; break;
            case 16:          bs1 = (const float*)d_in[i]; break;
            case 5 * 16 * 8:  b2  = (const float*)d_in[i]; break;
            case 16 * 8:      r2  = (const float*)d_in[i]; break;
            case 8:           bs2 = (const float*)d_in[i]; break;
            case 15:          if (!c1) c1 = (const float*)d_in[i];
                              else     c2 = (const float*)d_in[i]; break;
            default: break;
        }
    }
    const int4* src4 = (const int4*)ei;
    const int4* dst4 = (const int4*)(ei + EE);
    const int4* et4  = (const int4*)et;
    float* out = (float*)d_out;

    // Lazy resource creation (first call is uncaptured correctness run).
    static cudaStream_t s_side = nullptr;
    static cudaEvent_t  e_prep = nullptr, e_cpy = nullptr;
    static void* a_cpack = nullptr;
    if (!s_side) {
        cudaStreamCreateWithFlags(&s_side, cudaStreamNonBlocking);
        cudaEventCreateWithFlags(&e_prep, cudaEventDisableTiming);
        cudaEventCreateWithFlags(&e_cpy,  cudaEventDisableTiming);
        cudaGetSymbolAddress(&a_cpack, g_cpack);
    }

    const int T = 256;

    prep1<<<(NN + T - 1) / T, T>>>(x, b1, c1, b2, c2, r1, bs1, r2, bs2);

    // Single weight memcpy on side stream — hidden behind scatter1.
    cudaEventRecord(e_prep, 0);
    cudaStreamWaitEvent(s_side, e_prep, 0);
    cudaMemcpyToSymbolAsync(c_pack, a_cpack, 728 * sizeof(float), 0,
                            cudaMemcpyDeviceToDevice, s_side);
    cudaEventRecord(e_cpy, s_side);

    scatter1<<<(EE / 4) / T, T>>>(src4, dst4, et4);

    cudaStreamWaitEvent(0, e_cpy, 0);
    fin1dense2<<<(NN + T - 1) / T, T>>>();
    scatter2<<<(EE / 4) / T, T>>>(src4, dst4, et4);
    finalize2<<<(NN + T - 1) / T, T>>>(out);
    (void)out_size;
}

// round 15
// speedup vs baseline: 2.2229x; 1.0044x over previous
#include <cuda_runtime.h>
#include <cuda_fp16.h>
#include <cuda_bf16.h>
#include <cstdint>

#define NN 200000
#define EE 6400000
// R=3, B=5, H=16, C=8

// ---------------- scratch ----------------------------------------------------
__device__ float4 g_x4     [NN];          // (x0, x1, x2, 1.0) per node
__device__ float4 g_sx     [3 * NN];      // per (r,dst): sum x + count in .w
__device__ uint4  g_xw2h   [3 * NN];      // [r][n][8] layer2 messages, fp16 (16B)
__device__ uint4  g_sums2h [3 * NN];      // per (r,dst) sums, layer2, fp16 (16B)
__device__ uint4  g_rootx2h[NN];          // h@root2 + bias2, fp16 (16B)
__device__ float  g_cpack  [728];         // staging for all weights

// ---------------- constant weights (one packed bank, one memcpy) -------------
// Layout: W1[144] | W2[384] | root1[48] | bias1[16] | root2[128] | bias2[8]
__constant__ float c_pack[728];
#define CW1(i) c_pack[(i)]
#define CW2(i) c_pack[144 + (i)]
#define CR1(i) c_pack[528 + (i)]
#define CB1(i) c_pack[576 + (i)]
#define CR2(i) c_pack[592 + (i)]
#define CB2(i) c_pack[720 + (i)]

// ---------------- vectorized global reductions -------------------------------
__device__ __forceinline__ void red_add_v4(float4* addr, float4 v) {
    asm volatile("red.relaxed.gpu.global.add.v4.f32 [%0], {%1,%2,%3,%4};"
                 :: "l"(addr), "f"(v.x), "f"(v.y), "f"(v.z), "f"(v.w) : "memory");
}
__device__ __forceinline__ void red_add_v4h2(uint4* addr, uint4 v) {
    asm volatile("red.relaxed.gpu.global.add.noftz.v4.f16x2 [%0], {%1,%2,%3,%4};"
                 :: "l"(addr), "r"(v.x), "r"(v.y), "r"(v.z), "r"(v.w) : "memory");
}

// ---------------- kernels ----------------------------------------------------

// Fused prep: pack x, zero g_sx, build weight pack (block 0).
__global__ void prep1(const float* __restrict__ x,
                      const float* __restrict__ b1, const float* __restrict__ c1,
                      const float* __restrict__ b2, const float* __restrict__ c2,
                      const float* __restrict__ r1, const float* __restrict__ bs1,
                      const float* __restrict__ r2, const float* __restrict__ bs2) {
    int n = blockIdx.x * blockDim.x + threadIdx.x;
    if (n < NN) {
        g_x4[n] = make_float4(x[n * 3 + 0], x[n * 3 + 1], x[n * 3 + 2], 1.0f);
        float4 z = make_float4(0.f, 0.f, 0.f, 0.f);
        g_sx[n] = z;
        g_sx[NN + n] = z;
        g_sx[2 * NN + n] = z;
    }
    if (blockIdx.x == 0) {
        for (int t = threadIdx.x; t < 144; t += blockDim.x) {  // W1: [r][i][o]
            int r = t / 48, rem = t % 48, i = rem / 16, o = rem % 16;
            float acc = 0.f;
            #pragma unroll
            for (int b = 0; b < 5; b++) acc += c1[r * 5 + b] * b1[(b * 3 + i) * 16 + o];
            g_cpack[t] = acc;
        }
        for (int t = threadIdx.x; t < 384; t += blockDim.x) {  // W2: [r][k][c]
            int r = t / 128, rem = t % 128, k = rem / 8, c = rem % 8;
            float acc = 0.f;
            #pragma unroll
            for (int b = 0; b < 5; b++) acc += c2[r * 5 + b] * b2[(b * 16 + k) * 8 + c];
            g_cpack[144 + t] = acc;
        }
        for (int t = threadIdx.x; t < 48; t += blockDim.x)  g_cpack[528 + t] = r1[t];
        for (int t = threadIdx.x; t < 16; t += blockDim.x)  g_cpack[576 + t] = bs1[t];
        for (int t = threadIdx.x; t < 128; t += blockDim.x) g_cpack[592 + t] = r2[t];
        for (int t = threadIdx.x; t < 8; t += blockDim.x)   g_cpack[720 + t] = bs2[t];
    }
}

// Layer-1 edge scatter: 4 edges/thread, int4 index loads (pure R9 form).
__global__ void scatter1(const int4* __restrict__ src4, const int4* __restrict__ dst4,
                         const int4* __restrict__ et4) {
    int t = blockIdx.x * blockDim.x + threadIdx.x;
    if (t >= EE / 4) return;
    int4 s = src4[t], d = dst4[t], r = et4[t];
    float4 v0 = __ldg(&g_x4[s.x]);
    float4 v1 = __ldg(&g_x4[s.y]);
    float4 v2 = __ldg(&g_x4[s.z]);
    float4 v3 = __ldg(&g_x4[s.w]);
    red_add_v4(&g_sx[r.x * NN + d.x], v0);
    red_add_v4(&g_sx[r.y * NN + d.y], v1);
    red_add_v4(&g_sx[r.z * NN + d.z], v2);
    red_add_v4(&g_sx[r.w * NN + d.w], v3);
}

// Fused layer-1 finalize + layer-2 dense: 7 STG.128/node
// (3 fp16 messages + 3 sums2h zero + 1 fp16 rootx2).
__global__ void fin1dense2() {
    int n = blockIdx.x * blockDim.x + threadIdx.x;
    if (n >= NN) return;
    float h[16];
    #pragma unroll
    for (int o = 0; o < 16; o++) h[o] = CB1(o);
    float4 xv = g_x4[n];
    float xi[3] = {xv.x, xv.y, xv.z};
    #pragma unroll
    for (int i = 0; i < 3; i++)
        #pragma unroll
        for (int o = 0; o < 16; o++) h[o] += xi[i] * CR1(i * 16 + o);
    #pragma unroll
    for (int r = 0; r < 3; r++) {
        float4 s = g_sx[r * NN + n];
        float inv = 1.0f / fmaxf(s.w, 1.0f);
        float m[3] = {s.x * inv, s.y * inv, s.z * inv};
        #pragma unroll
        for (int i = 0; i < 3; i++)
            #pragma unroll
            for (int o = 0; o < 16; o++) h[o] += m[i] * CW1(r * 48 + i * 16 + o);
    }
    #pragma unroll
    for (int o = 0; o < 16; o++) h[o] = fmaxf(h[o], 0.f);

    uint4 z = make_uint4(0u, 0u, 0u, 0u);
    #pragma unroll
    for (int r = 0; r < 3; r++) {
        float acc[8];
        #pragma unroll
        for (int c = 0; c < 8; c++) acc[c] = 0.f;
        #pragma unroll
        for (int k = 0; k < 16; k++)
            #pragma unroll
            for (int c = 0; c < 8; c++) acc[c] += h[k] * CW2(r * 128 + k * 8 + c);
        __half2 p0 = __float22half2_rn(make_float2(acc[0], acc[1]));
        __half2 p1 = __float22half2_rn(make_float2(acc[2], acc[3]));
        __half2 p2 = __float22half2_rn(make_float2(acc[4], acc[5]));
        __half2 p3 = __float22half2_rn(make_float2(acc[6], acc[7]));
        uint4 packed;
        packed.x = *reinterpret_cast<unsigned*>(&p0);
        packed.y = *reinterpret_cast<unsigned*>(&p1);
        packed.z = *reinterpret_cast<unsigned*>(&p2);
        packed.w = *reinterpret_cast<unsigned*>(&p3);
        g_xw2h[r * NN + n] = packed;
        g_sums2h[r * NN + n] = z;          // zero fp16 accumulator inline (R9)
    }
    float acc[8];
    #pragma unroll
    for (int c = 0; c < 8; c++) acc[c] = CB2(c);
    #pragma unroll
    for (int k = 0; k < 16; k++)
        #pragma unroll
        for (int c = 0; c < 8; c++) acc[c] += h[k] * CR2(k * 8 + c);
    __half2 q0 = __float22half2_rn(make_float2(acc[0], acc[1]));
    __half2 q1 = __float22half2_rn(make_float2(acc[2], acc[3]));
    __half2 q2 = __float22half2_rn(make_float2(acc[4], acc[5]));
    __half2 q3 = __float22half2_rn(make_float2(acc[6], acc[7]));
    uint4 rp;
    rp.x = *reinterpret_cast<unsigned*>(&q0);
    rp.y = *reinterpret_cast<unsigned*>(&q1);
    rp.z = *reinterpret_cast<unsigned*>(&q2);
    rp.w = *reinterpret_cast<unsigned*>(&q3);
    g_rootx2h[n] = rp;
}

// Layer-2 edge scatter: 4 edges/thread, 1 gather + 1 fp16 RED per edge.
__global__ void scatter2(const int4* __restrict__ src4, const int4* __restrict__ dst4,
                         const int4* __restrict__ et4) {
    int t = blockIdx.x * blockDim.x + threadIdx.x;
    if (t >= EE / 4) return;
    int4 s = src4[t], d = dst4[t], r = et4[t];
    uint4 p0 = __ldg(&g_xw2h[r.x * NN + s.x]);
    uint4 p1 = __ldg(&g_xw2h[r.y * NN + s.y]);
    uint4 p2 = __ldg(&g_xw2h[r.z * NN + s.z]);
    uint4 p3 = __ldg(&g_xw2h[r.w * NN + s.w]);
    red_add_v4h2(&g_sums2h[r.x * NN + d.x], p0);
    red_add_v4h2(&g_sums2h[r.y * NN + d.y], p1);
    red_add_v4h2(&g_sums2h[r.z * NN + d.z], p2);
    red_add_v4h2(&g_sums2h[r.w * NN + d.w], p3);
}

// Layer-2 finalize + log_softmax. One thread per node. Counts from g_sx.w.
__global__ void finalize2(float* __restrict__ out) {
    int n = blockIdx.x * blockDim.x + threadIdx.x;
    if (n >= NN) return;
    float v[8];
    {
        uint4 rp = g_rootx2h[n];
        float2 a = __half22float2(*reinterpret_cast<__half2*>(&rp.x));
        float2 b = __half22float2(*reinterpret_cast<__half2*>(&rp.y));
        float2 c = __half22float2(*reinterpret_cast<__half2*>(&rp.z));
        float2 dd = __half22float2(*reinterpret_cast<__half2*>(&rp.w));
        v[0]=a.x; v[1]=a.y; v[2]=b.x; v[3]=b.y;
        v[4]=c.x; v[5]=c.y; v[6]=dd.x; v[7]=dd.y;
    }
    #pragma unroll
    for (int r = 0; r < 3; r++) {
        float inv = 1.0f / fmaxf(g_sx[r * NN + n].w, 1.0f);
        uint4 p = g_sums2h[r * NN + n];
        float2 f0 = __half22float2(*reinterpret_cast<__half2*>(&p.x));
        float2 f1 = __half22float2(*reinterpret_cast<__half2*>(&p.y));
        float2 f2 = __half22float2(*reinterpret_cast<__half2*>(&p.z));
        float2 f3 = __half22float2(*reinterpret_cast<__half2*>(&p.w));
        v[0] += f0.x*inv; v[1] += f0.y*inv; v[2] += f1.x*inv; v[3] += f1.y*inv;
        v[4] += f2.x*inv; v[5] += f2.y*inv; v[6] += f3.x*inv; v[7] += f3.y*inv;
    }
    float m = v[0];
    #pragma unroll
    for (int i = 1; i < 8; i++) m = fmaxf(m, v[i]);
    float s = 0.f;
    #pragma unroll
    for (int i = 0; i < 8; i++) s += expf(v[i] - m);
    float lse = m + logf(s);
    float4* o = (float4*)(out + (size_t)n * 8);
    o[0] = make_float4(v[0]-lse, v[1]-lse, v[2]-lse, v[3]-lse);
    o[1] = make_float4(v[4]-lse, v[5]-lse, v[6]-lse, v[7]-lse);
}

// ---------------- host -------------------------------------------------------
extern "C" void kernel_launch(void* const* d_in, const int* in_sizes, int n_in,
                              void* d_out, int out_size) {
    const float *x = nullptr, *b1 = nullptr, *c1 = nullptr, *r1 = nullptr, *bs1 = nullptr;
    const float *b2 = nullptr, *c2 = nullptr, *r2 = nullptr, *bs2 = nullptr;
    const int *ei = nullptr, *et = nullptr;
    for (int i = 0; i < n_in; i++) {
        switch (in_sizes[i]) {
            case NN * 3:      x   = (const float*)d_in[i]; break;
            case 2 * EE:      ei  = (const int*)d_in[i];   break;
            case EE:          et  = (const int*)d_in[i];   break;
            case 5 * 3 * 16:  b1  = (const float*)d_in[i]; break;
            case 3 * 16:      r1  = (const float*)d_in[i]; break;
            case 16:          bs1 = (const float*)d_in[i]; break;
            case 5 * 16 * 8:  b2  = (const float*)d_in[i]; break;
            case 16 * 8:      r2  = (const float*)d_in[i]; break;
            case 8:           bs2 = (const float*)d_in[i]; break;
            case 15:          if (!c1) c1 = (const float*)d_in[i];
                              else     c2 = (const float*)d_in[i]; break;
            default: break;
        }
    }
    const int4* src4 = (const int4*)ei;
    const int4* dst4 = (const int4*)(ei + EE);
    const int4* et4  = (const int4*)et;
    float* out = (float*)d_out;

    // Lazy resource creation (first call is uncaptured correctness run).
    static cudaStream_t s_side = nullptr;
    static cudaEvent_t  e_prep = nullptr, e_cpy = nullptr;
    static void* a_cpack = nullptr;
    if (!s_side) {
        cudaStreamCreateWithFlags(&s_side, cudaStreamNonBlocking);
        cudaEventCreateWithFlags(&e_prep, cudaEventDisableTiming);
        cudaEventCreateWithFlags(&e_cpy,  cudaEventDisableTiming);
        cudaGetSymbolAddress(&a_cpack, g_cpack);
    }

    const int T = 256;

    prep1<<<(NN + T - 1) / T, T>>>(x, b1, c1, b2, c2, r1, bs1, r2, bs2);

    // Single weight memcpy on side stream — hidden behind scatter1.
    cudaEventRecord(e_prep, 0);
    cudaStreamWaitEvent(s_side, e_prep, 0);
    cudaMemcpyToSymbolAsync(c_pack, a_cpack, 728 * sizeof(float), 0,
                            cudaMemcpyDeviceToDevice, s_side);
    cudaEventRecord(e_cpy, s_side);

    scatter1<<<(EE / 4) / T, T>>>(src4, dst4, et4);

    cudaStreamWaitEvent(0, e_cpy, 0);
    fin1dense2<<<(NN + T - 1) / T, T>>>();
    scatter2<<<(EE / 4) / T, T>>>(src4, dst4, et4);
    finalize2<<<(NN + T - 1) / T, T>>>(out);
    (void)out_size;
}

// round 16
// speedup vs baseline: 2.2666x; 1.0197x over previous
#include <cuda_runtime.h>
#include <cuda_fp16.h>
#include <cuda_bf16.h>
#include <cstdint>

#define NN 200000
#define EE 6400000
// R=3, B=5, H=16, C=8

// ---------------- scratch ----------------------------------------------------
__device__ float4 g_x4     [NN];          // (x0, x1, x2, 1.0) f32 — fin1dense2 path
__device__ unsigned long long g_x2h[NN];  // (x0, x1, x2) fp16 packed, 8B — scatter1 gather
__device__ float4 g_sx     [3 * NN];      // per (r,dst): sum x + count in .w
__device__ uint4  g_xw2h   [3 * NN];      // [r][n][8] layer2 messages, fp16 (16B)
__device__ uint4  g_sums2h [3 * NN];      // per (r,dst) sums, layer2, fp16 (16B)
__device__ uint4  g_rootx2h[NN];          // h@root2 + bias2, fp16 (16B)
__device__ float  g_cpack  [728];         // staging for all weights

// ---------------- constant weights (one packed bank, one memcpy) -------------
// Layout: W1[144] | W2[384] | root1[48] | bias1[16] | root2[128] | bias2[8]
__constant__ float c_pack[728];
#define CW1(i) c_pack[(i)]
#define CW2(i) c_pack[144 + (i)]
#define CR1(i) c_pack[528 + (i)]
#define CB1(i) c_pack[576 + (i)]
#define CR2(i) c_pack[592 + (i)]
#define CB2(i) c_pack[720 + (i)]

// ---------------- vectorized global reductions -------------------------------
__device__ __forceinline__ void red_add_v4(float4* addr, float4 v) {
    asm volatile("red.relaxed.gpu.global.add.v4.f32 [%0], {%1,%2,%3,%4};"
                 :: "l"(addr), "f"(v.x), "f"(v.y), "f"(v.z), "f"(v.w) : "memory");
}
__device__ __forceinline__ void red_add_v4h2(uint4* addr, uint4 v) {
    asm volatile("red.relaxed.gpu.global.add.noftz.v4.f16x2 [%0], {%1,%2,%3,%4};"
                 :: "l"(addr), "r"(v.x), "r"(v.y), "r"(v.z), "r"(v.w) : "memory");
}

// Unpack fp16 (x0,x1,x2) + append count lane 1.0f.
__device__ __forceinline__ float4 unpack_x(unsigned long long v) {
    unsigned lo = (unsigned)v;
    __half2 h01 = *reinterpret_cast<__half2*>(&lo);
    float2 f01 = __half22float2(h01);
    float f2 = __half2float(__ushort_as_half((unsigned short)(v >> 32)));
    return make_float4(f01.x, f01.y, f2, 1.0f);
}

// ---------------- kernels ----------------------------------------------------

// Fused prep: pack x (f32 + fp16), zero g_sx, build weight pack (block 0).
__global__ void prep1(const float* __restrict__ x,
                      const float* __restrict__ b1, const float* __restrict__ c1,
                      const float* __restrict__ b2, const float* __restrict__ c2,
                      const float* __restrict__ r1, const float* __restrict__ bs1,
                      const float* __restrict__ r2, const float* __restrict__ bs2) {
    int n = blockIdx.x * blockDim.x + threadIdx.x;
    if (n < NN) {
        float x0 = x[n * 3 + 0], x1 = x[n * 3 + 1], x2 = x[n * 3 + 2];
        g_x4[n] = make_float4(x0, x1, x2, 1.0f);
        g_x2h[n] = (unsigned long long)__half_as_ushort(__float2half_rn(x0))
                 | ((unsigned long long)__half_as_ushort(__float2half_rn(x1)) << 16)
                 | ((unsigned long long)__half_as_ushort(__float2half_rn(x2)) << 32);
        float4 z = make_float4(0.f, 0.f, 0.f, 0.f);
        g_sx[n] = z;
        g_sx[NN + n] = z;
        g_sx[2 * NN + n] = z;
    }
    if (blockIdx.x == 0) {
        for (int t = threadIdx.x; t < 144; t += blockDim.x) {  // W1: [r][i][o]
            int r = t / 48, rem = t % 48, i = rem / 16, o = rem % 16;
            float acc = 0.f;
            #pragma unroll
            for (int b = 0; b < 5; b++) acc += c1[r * 5 + b] * b1[(b * 3 + i) * 16 + o];
            g_cpack[t] = acc;
        }
        for (int t = threadIdx.x; t < 384; t += blockDim.x) {  // W2: [r][k][c]
            int r = t / 128, rem = t % 128, k = rem / 8, c = rem % 8;
            float acc = 0.f;
            #pragma unroll
            for (int b = 0; b < 5; b++) acc += c2[r * 5 + b] * b2[(b * 16 + k) * 8 + c];
            g_cpack[144 + t] = acc;
        }
        for (int t = threadIdx.x; t < 48; t += blockDim.x)  g_cpack[528 + t] = r1[t];
        for (int t = threadIdx.x; t < 16; t += blockDim.x)  g_cpack[576 + t] = bs1[t];
        for (int t = threadIdx.x; t < 128; t += blockDim.x) g_cpack[592 + t] = r2[t];
        for (int t = threadIdx.x; t < 8; t += blockDim.x)   g_cpack[720 + t] = bs2[t];
    }
}

// Layer-1 edge scatter: 4 edges/thread; 8B fp16 gather (1.6MB table, L1-cacheable),
// f32 RED with count fused in .w.
__global__ void scatter1(const int4* __restrict__ src4, const int4* __restrict__ dst4,
                         const int4* __restrict__ et4) {
    int t = blockIdx.x * blockDim.x + threadIdx.x;
    if (t >= EE / 4) return;
    int4 s = src4[t], d = dst4[t], r = et4[t];
    unsigned long long w0 = __ldg(&g_x2h[s.x]);
    unsigned long long w1 = __ldg(&g_x2h[s.y]);
    unsigned long long w2 = __ldg(&g_x2h[s.z]);
    unsigned long long w3 = __ldg(&g_x2h[s.w]);
    red_add_v4(&g_sx[r.x * NN + d.x], unpack_x(w0));
    red_add_v4(&g_sx[r.y * NN + d.y], unpack_x(w1));
    red_add_v4(&g_sx[r.z * NN + d.z], unpack_x(w2));
    red_add_v4(&g_sx[r.w * NN + d.w], unpack_x(w3));
}

// Fused layer-1 finalize + layer-2 dense: 7 STG.128/node
// (3 fp16 messages + 3 sums2h zero + 1 fp16 rootx2).
__global__ void fin1dense2() {
    int n = blockIdx.x * blockDim.x + threadIdx.x;
    if (n >= NN) return;
    float h[16];
    #pragma unroll
    for (int o = 0; o < 16; o++) h[o] = CB1(o);
    float4 xv = g_x4[n];
    float xi[3] = {xv.x, xv.y, xv.z};
    #pragma unroll
    for (int i = 0; i < 3; i++)
        #pragma unroll
        for (int o = 0; o < 16; o++) h[o] += xi[i] * CR1(i * 16 + o);
    #pragma unroll
    for (int r = 0; r < 3; r++) {
        float4 s = g_sx[r * NN + n];
        float inv = 1.0f / fmaxf(s.w, 1.0f);
        float m[3] = {s.x * inv, s.y * inv, s.z * inv};
        #pragma unroll
        for (int i = 0; i < 3; i++)
            #pragma unroll
            for (int o = 0; o < 16; o++) h[o] += m[i] * CW1(r * 48 + i * 16 + o);
    }
    #pragma unroll
    for (int o = 0; o < 16; o++) h[o] = fmaxf(h[o], 0.f);

    uint4 z = make_uint4(0u, 0u, 0u, 0u);
    #pragma unroll
    for (int r = 0; r < 3; r++) {
        float acc[8];
        #pragma unroll
        for (int c = 0; c < 8; c++) acc[c] = 0.f;
        #pragma unroll
        for (int k = 0; k < 16; k++)
            #pragma unroll
            for (int c = 0; c < 8; c++) acc[c] += h[k] * CW2(r * 128 + k * 8 + c);
        __half2 p0 = __float22half2_rn(make_float2(acc[0], acc[1]));
        __half2 p1 = __float22half2_rn(make_float2(acc[2], acc[3]));
        __half2 p2 = __float22half2_rn(make_float2(acc[4], acc[5]));
        __half2 p3 = __float22half2_rn(make_float2(acc[6], acc[7]));
        uint4 packed;
        packed.x = *reinterpret_cast<unsigned*>(&p0);
        packed.y = *reinterpret_cast<unsigned*>(&p1);
        packed.z = *reinterpret_cast<unsigned*>(&p2);
        packed.w = *reinterpret_cast<unsigned*>(&p3);
        g_xw2h[r * NN + n] = packed;
        g_sums2h[r * NN + n] = z;          // zero fp16 accumulator inline
    }
    float acc[8];
    #pragma unroll
    for (int c = 0; c < 8; c++) acc[c] = CB2(c);
    #pragma unroll
    for (int k = 0; k < 16; k++)
        #pragma unroll
        for (int c = 0; c < 8; c++) acc[c] += h[k] * CR2(k * 8 + c);
    __half2 q0 = __float22half2_rn(make_float2(acc[0], acc[1]));
    __half2 q1 = __float22half2_rn(make_float2(acc[2], acc[3]));
    __half2 q2 = __float22half2_rn(make_float2(acc[4], acc[5]));
    __half2 q3 = __float22half2_rn(make_float2(acc[6], acc[7]));
    uint4 rp;
    rp.x = *reinterpret_cast<unsigned*>(&q0);
    rp.y = *reinterpret_cast<unsigned*>(&q1);
    rp.z = *reinterpret_cast<unsigned*>(&q2);
    rp.w = *reinterpret_cast<unsigned*>(&q3);
    g_rootx2h[n] = rp;
}

// Layer-2 edge scatter: 4 edges/thread, 1 gather + 1 fp16 RED per edge.
__global__ void scatter2(const int4* __restrict__ src4, const int4* __restrict__ dst4,
                         const int4* __restrict__ et4) {
    int t = blockIdx.x * blockDim.x + threadIdx.x;
    if (t >= EE / 4) return;
    int4 s = src4[t], d = dst4[t], r = et4[t];
    uint4 p0 = __ldg(&g_xw2h[r.x * NN + s.x]);
    uint4 p1 = __ldg(&g_xw2h[r.y * NN + s.y]);
    uint4 p2 = __ldg(&g_xw2h[r.z * NN + s.z]);
    uint4 p3 = __ldg(&g_xw2h[r.w * NN + s.w]);
    red_add_v4h2(&g_sums2h[r.x * NN + d.x], p0);
    red_add_v4h2(&g_sums2h[r.y * NN + d.y], p1);
    red_add_v4h2(&g_sums2h[r.z * NN + d.z], p2);
    red_add_v4h2(&g_sums2h[r.w * NN + d.w], p3);
}

// Layer-2 finalize + log_softmax. One thread per node. Counts from g_sx.w.
__global__ void finalize2(float* __restrict__ out) {
    int n = blockIdx.x * blockDim.x + threadIdx.x;
    if (n >= NN) return;
    float v[8];
    {
        uint4 rp = g_rootx2h[n];
        float2 a = __half22float2(*reinterpret_cast<__half2*>(&rp.x));
        float2 b = __half22float2(*reinterpret_cast<__half2*>(&rp.y));
        float2 c = __half22float2(*reinterpret_cast<__half2*>(&rp.z));
        float2 dd = __half22float2(*reinterpret_cast<__half2*>(&rp.w));
        v[0]=a.x; v[1]=a.y; v[2]=b.x; v[3]=b.y;
        v[4]=c.x; v[5]=c.y; v[6]=dd.x; v[7]=dd.y;
    }
    #pragma unroll
    for (int r = 0; r < 3; r++) {
        float inv = 1.0f / fmaxf(g_sx[r * NN + n].w, 1.0f);
        uint4 p = g_sums2h[r * NN + n];
        float2 f0 = __half22float2(*reinterpret_cast<__half2*>(&p.x));
        float2 f1 = __half22float2(*reinterpret_cast<__half2*>(&p.y));
        float2 f2 = __half22float2(*reinterpret_cast<__half2*>(&p.z));
        float2 f3 = __half22float2(*reinterpret_cast<__half2*>(&p.w));
        v[0] += f0.x*inv; v[1] += f0.y*inv; v[2] += f1.x*inv; v[3] += f1.y*inv;
        v[4] += f2.x*inv; v[5] += f2.y*inv; v[6] += f3.x*inv; v[7] += f3.y*inv;
    }
    float m = v[0];
    #pragma unroll
    for (int i = 1; i < 8; i++) m = fmaxf(m, v[i]);
    float s = 0.f;
    #pragma unroll
    for (int i = 0; i < 8; i++) s += expf(v[i] - m);
    float lse = m + logf(s);
    float4* o = (float4*)(out + (size_t)n * 8);
    o[0] = make_float4(v[0]-lse, v[1]-lse, v[2]-lse, v[3]-lse);
    o[1] = make_float4(v[4]-lse, v[5]-lse, v[6]-lse, v[7]-lse);
}

// ---------------- host -------------------------------------------------------
extern "C" void kernel_launch(void* const* d_in, const int* in_sizes, int n_in,
                              void* d_out, int out_size) {
    const float *x = nullptr, *b1 = nullptr, *c1 = nullptr, *r1 = nullptr, *bs1 = nullptr;
    const float *b2 = nullptr, *c2 = nullptr, *r2 = nullptr, *bs2 = nullptr;
    const int *ei = nullptr, *et = nullptr;
    for (int i = 0; i < n_in; i++) {
        switch (in_sizes[i]) {
            case NN * 3:      x   = (const float*)d_in[i]; break;
            case 2 * EE:      ei  = (const int*)d_in[i];   break;
            case EE:          et  = (const int*)d_in[i];   break;
            case 5 * 3 * 16:  b1  = (const float*)d_in[i]; break;
            case 3 * 16:      r1  = (const float*)d_in[i]; break;
            case 16:          bs1 = (const float*)d_in[i]; break;
            case 5 * 16 * 8:  b2  = (const float*)d_in[i]; break;
            case 16 * 8:      r2  = (const float*)d_in[i]; break;
            case 8:           bs2 = (const float*)d_in[i]; break;
            case 15:          if (!c1) c1 = (const float*)d_in[i];
                              else     c2 = (const float*)d_in[i]; break;
            default: break;
        }
    }
    const int4* src4 = (const int4*)ei;
    const int4* dst4 = (const int4*)(ei + EE);
    const int4* et4  = (const int4*)et;
    float* out = (float*)d_out;

    // Lazy resource creation (first call is uncaptured correctness run).
    static cudaStream_t s_side = nullptr;
    static cudaEvent_t  e_prep = nullptr, e_cpy = nullptr;
    static void* a_cpack = nullptr;
    if (!s_side) {
        cudaStreamCreateWithFlags(&s_side, cudaStreamNonBlocking);
        cudaEventCreateWithFlags(&e_prep, cudaEventDisableTiming);
        cudaEventCreateWithFlags(&e_cpy,  cudaEventDisableTiming);
        cudaGetSymbolAddress(&a_cpack, g_cpack);
    }

    const int T = 256;

    prep1<<<(NN + T - 1) / T, T>>>(x, b1, c1, b2, c2, r1, bs1, r2, bs2);

    // Single weight memcpy on side stream — hidden behind scatter1.
    cudaEventRecord(e_prep, 0);
    cudaStreamWaitEvent(s_side, e_prep, 0);
    cudaMemcpyToSymbolAsync(c_pack, a_cpack, 728 * sizeof(float), 0,
                            cudaMemcpyDeviceToDevice, s_side);
    cudaEventRecord(e_cpy, s_side);

    scatter1<<<(EE / 4) / T, T>>>(src4, dst4, et4);

    cudaStreamWaitEvent(0, e_cpy, 0);
    fin1dense2<<<(NN + T - 1) / T, T>>>();
    scatter2<<<(EE / 4) / T, T>>>(src4, dst4, et4);
    finalize2<<<(NN + T - 1) / T, T>>>(out);
    (void)out_size;
}